// round 2
// baseline (speedup 1.0000x reference)
#include <cuda_runtime.h>

#define NN 100000
#define EMAX 3300000
#define H1D 4
#define CD 8
#define NEG 0.2f
#define NB ((NN + 255) / 256)   // 391 scan blocks

// Persistent device scratch (no allocation in kernel_launch).
__device__ float g_ws[H1D], g_wd[H1D];
__device__ int   g_cnt[NN];
__device__ int   g_off[NN];
__device__ int   g_cur[NN];
__device__ int   g_srcs[EMAX];
__device__ int   g_part[512];
__device__ float g_node2[NN * 12];   // per node: h2[0..7], als, ald, pad, pad

__device__ __forceinline__ float wred32(float v) {
    v += __shfl_xor_sync(0xffffffffu, v, 16);
    v += __shfl_xor_sync(0xffffffffu, v, 8);
    v += __shfl_xor_sync(0xffffffffu, v, 4);
    v += __shfl_xor_sync(0xffffffffu, v, 2);
    v += __shfl_xor_sync(0xffffffffu, v, 1);
    return v;
}

// ---------------------------------------------------------------------------
// 1) zero histogram counters
// ---------------------------------------------------------------------------
__global__ void k_zero() {
    int i = blockIdx.x * blockDim.x + threadIdx.x;
    if (i < NN) g_cnt[i] = 0;
}

// ---------------------------------------------------------------------------
// 2) histogram of dst
// ---------------------------------------------------------------------------
__global__ void __launch_bounds__(256) k_hist(const int* __restrict__ dst, int E) {
    int t = blockIdx.x * blockDim.x + threadIdx.x;
    if (t < E) atomicAdd(&g_cnt[dst[t]], 1);
}

// ---------------------------------------------------------------------------
// 3) scan part 1: per-block sums of g_cnt
// ---------------------------------------------------------------------------
__global__ void __launch_bounds__(256) k_scan1() {
    __shared__ int sh[256];
    int t = threadIdx.x;
    int i = blockIdx.x * 256 + t;
    sh[t] = (i < NN) ? g_cnt[i] : 0;
    __syncthreads();
    for (int o = 128; o > 0; o >>= 1) {
        if (t < o) sh[t] += sh[t + o];
        __syncthreads();
    }
    if (t == 0) g_part[blockIdx.x] = sh[0];
}

// ---------------------------------------------------------------------------
// 4) scan part 2: exclusive scan of block sums (single block) + ws/wd prep
// ---------------------------------------------------------------------------
__global__ void __launch_bounds__(512) k_scan2(const float* __restrict__ W1,
                                               const float* __restrict__ as1,
                                               const float* __restrict__ ad1) {
    __shared__ int sh[512];
    int t = threadIdx.x;
    int v = (t < NB) ? g_part[t] : 0;
    sh[t] = v;
    __syncthreads();
    for (int o = 1; o < 512; o <<= 1) {
        int a = (t >= o) ? sh[t - o] : 0;
        __syncthreads();
        sh[t] += a;
        __syncthreads();
    }
    g_part[t] = sh[t] - v;  // exclusive
    if (t < H1D) {
        float s = 0.0f, d = 0.0f;
#pragma unroll
        for (int c = 0; c < CD; c++) {
            float w = W1[t * CD + c];
            s += w * as1[t * CD + c];
            d += w * ad1[t * CD + c];
        }
        g_ws[t] = s;
        g_wd[t] = d;
    }
}

// ---------------------------------------------------------------------------
// 5) scan part 3: block-local exclusive scan + block offset -> g_off, g_cur
// ---------------------------------------------------------------------------
__global__ void __launch_bounds__(256) k_scan3() {
    __shared__ int sh[256];
    int t = threadIdx.x;
    int i = blockIdx.x * 256 + t;
    int v = (i < NN) ? g_cnt[i] : 0;
    sh[t] = v;
    __syncthreads();
    for (int o = 1; o < 256; o <<= 1) {
        int a = (t >= o) ? sh[t - o] : 0;
        __syncthreads();
        sh[t] += a;
        __syncthreads();
    }
    if (i < NN) {
        int off = g_part[blockIdx.x] + sh[t] - v;
        g_off[i] = off;
        g_cur[i] = off;
    }
}

// ---------------------------------------------------------------------------
// 6) scatter src indices into CSR buckets
// ---------------------------------------------------------------------------
__global__ void __launch_bounds__(256) k_scatter(const int* __restrict__ src,
                                                 const int* __restrict__ dst,
                                                 int E) {
    int t = blockIdx.x * blockDim.x + threadIdx.x;
    if (t >= E) return;
    int d = dst[t];
    int slot = atomicAdd(&g_cur[d], 1);
    g_srcs[slot] = src[t];
}

// ---------------------------------------------------------------------------
// 7) layer-1 gather + epilogue (fused GAT1 softmax-agg + relu + W2 + logits)
//    one warp per node
// ---------------------------------------------------------------------------
__global__ void __launch_bounds__(256) k_l1mid(const float* __restrict__ x,
                                               const float* __restrict__ W1,
                                               const float* __restrict__ b1,
                                               const float* __restrict__ W2,
                                               const float* __restrict__ as2,
                                               const float* __restrict__ ad2) {
    __shared__ float sW2[256], sW1[32], sb1[32], sas2[8], sad2[8];
    int tid = threadIdx.x;
    sW2[tid] = W2[tid];
    if (tid < 32) { sW1[tid] = W1[tid]; sb1[tid] = b1[tid]; }
    if (tid < 8)  { sas2[tid] = as2[tid]; sad2[tid] = ad2[tid]; }
    __syncthreads();

    int n = (blockIdx.x * blockDim.x + tid) >> 5;
    if (n >= NN) return;
    int lane = tid & 31;

    float wsr[H1D], wdr[H1D];
#pragma unroll
    for (int h = 0; h < H1D; h++) { wsr[h] = g_ws[h]; wdr[h] = g_wd[h]; }

    float xd = __ldg(&x[n]);
    float S[H1D] = {0, 0, 0, 0};
    float T[H1D] = {0, 0, 0, 0};

    // self-loop contribution
    if (lane == 0) {
#pragma unroll
        for (int h = 0; h < H1D; h++) {
            float e = xd * wsr[h] + xd * wdr[h];
            e = (e > 0.0f) ? e : NEG * e;
            float w = __expf(e);
            S[h] += w;
            T[h] += w * xd;
        }
    }

    int off = g_off[n];
    int end = off + g_cnt[n];
    for (int e = off + lane; e < end; e += 32) {
        int s = g_srcs[e];
        float xs = __ldg(&x[s]);
#pragma unroll
        for (int h = 0; h < H1D; h++) {
            float t = xs * wsr[h] + xd * wdr[h];
            t = (t > 0.0f) ? t : NEG * t;
            float w = __expf(t);
            S[h] += w;
            T[h] += w * xs;
        }
    }
#pragma unroll
    for (int h = 0; h < H1D; h++) { S[h] = wred32(S[h]); T[h] = wred32(T[h]); }

    float tsv[H1D];
#pragma unroll
    for (int h = 0; h < H1D; h++) tsv[h] = T[h] / S[h];

    // layer-1 output -> relu -> W2, per channel c = lane&7 (replicated x4)
    int c = lane & 7;
    float h2c = 0.0f;
#pragma unroll
    for (int hc = 0; hc < 32; hc++) {
        float r = fmaxf(sW1[hc] * tsv[hc >> 3] + sb1[hc], 0.0f);
        h2c += r * sW2[hc * 8 + c];
    }
    float als = h2c * sas2[c];
    float ald = h2c * sad2[c];
    als += __shfl_xor_sync(0xffffffffu, als, 4);
    als += __shfl_xor_sync(0xffffffffu, als, 2);
    als += __shfl_xor_sync(0xffffffffu, als, 1);
    ald += __shfl_xor_sync(0xffffffffu, ald, 4);
    ald += __shfl_xor_sync(0xffffffffu, ald, 2);
    ald += __shfl_xor_sync(0xffffffffu, ald, 1);

    float* nb = &g_node2[(size_t)n * 12];
    if (lane < 8) nb[c] = h2c;
    if (lane == 0) { nb[8] = als; nb[9] = ald; }
}

// ---------------------------------------------------------------------------
// 8) layer-2 gather + normalize + bias -> output (one warp per node)
// ---------------------------------------------------------------------------
__global__ void __launch_bounds__(256) k_l2out(float* __restrict__ out,
                                               const float* __restrict__ b2) {
    __shared__ float sb2[8];
    int tid = threadIdx.x;
    if (tid < 8) sb2[tid] = b2[tid];
    __syncthreads();

    int n = (blockIdx.x * blockDim.x + tid) >> 5;
    if (n >= NN) return;
    int lane = tid & 31;

    const float* nbd = &g_node2[(size_t)n * 12];
    float ald = __ldg(&nbd[9]);

    float acc0 = 0, acc1 = 0, acc2 = 0, acc3 = 0, acc4 = 0,
          acc5 = 0, acc6 = 0, acc7 = 0, acc8 = 0;

    // self-loop
    if (lane == 0) {
        float4 ha = *reinterpret_cast<const float4*>(nbd);
        float4 hb = *reinterpret_cast<const float4*>(nbd + 4);
        float als = nbd[8];
        float t = als + ald;
        t = (t > 0.0f) ? t : NEG * t;
        float w = __expf(t);
        acc0 = w;
        acc1 = w * ha.x; acc2 = w * ha.y; acc3 = w * ha.z; acc4 = w * ha.w;
        acc5 = w * hb.x; acc6 = w * hb.y; acc7 = w * hb.z; acc8 = w * hb.w;
    }

    int off = g_off[n];
    int end = off + g_cnt[n];
    for (int e = off + lane; e < end; e += 32) {
        int s = g_srcs[e];
        const float* r = &g_node2[(size_t)s * 12];
        float4 ha = *reinterpret_cast<const float4*>(r);
        float4 hb = *reinterpret_cast<const float4*>(r + 4);
        float als = __ldg(&r[8]);
        float t = als + ald;
        t = (t > 0.0f) ? t : NEG * t;
        float w = __expf(t);
        acc0 += w;
        acc1 += w * ha.x; acc2 += w * ha.y; acc3 += w * ha.z; acc4 += w * ha.w;
        acc5 += w * hb.x; acc6 += w * hb.y; acc7 += w * hb.z; acc8 += w * hb.w;
    }
    acc0 = wred32(acc0);
    acc1 = wred32(acc1); acc2 = wred32(acc2); acc3 = wred32(acc3); acc4 = wred32(acc4);
    acc5 = wred32(acc5); acc6 = wred32(acc6); acc7 = wred32(acc7); acc8 = wred32(acc8);

    if (lane == 0) {
        float inv = 1.0f / acc0;
        float4 o0 = make_float4(acc1 * inv + sb2[0], acc2 * inv + sb2[1],
                                acc3 * inv + sb2[2], acc4 * inv + sb2[3]);
        float4 o1 = make_float4(acc5 * inv + sb2[4], acc6 * inv + sb2[5],
                                acc7 * inv + sb2[6], acc8 * inv + sb2[7]);
        float4* ob = reinterpret_cast<float4*>(&out[(size_t)n * 8]);
        ob[0] = o0;
        ob[1] = o1;
    }
}

extern "C" void kernel_launch(void* const* d_in, const int* in_sizes, int n_in,
                              void* d_out, int out_size) {
    const float* x   = (const float*)d_in[0];
    const int*   ei  = (const int*)d_in[1];
    const float* W1  = (const float*)d_in[2];
    const float* as1 = (const float*)d_in[3];
    const float* ad1 = (const float*)d_in[4];
    const float* b1  = (const float*)d_in[5];
    const float* W2  = (const float*)d_in[6];
    const float* as2 = (const float*)d_in[7];
    const float* ad2 = (const float*)d_in[8];
    const float* b2  = (const float*)d_in[9];
    float* out = (float*)d_out;

    int E = in_sizes[1] / 2;
    const int* src = ei;
    const int* dst = ei + E;

    int eb = (E + 255) / 256;
    int nwarpb = (NN * 32 + 255) / 256;  // 12500 blocks, warp per node

    k_zero<<<(NN + 1023) / 1024, 1024>>>();
    k_hist<<<eb, 256>>>(dst, E);
    k_scan1<<<NB, 256>>>();
    k_scan2<<<1, 512>>>(W1, as1, ad1);
    k_scan3<<<NB, 256>>>();
    k_scatter<<<eb, 256>>>(src, dst, E);
    k_l1mid<<<nwarpb, 256>>>(x, W1, b1, W2, as2, ad2);
    k_l2out<<<nwarpb, 256>>>(out, b2);
}

// round 4
// speedup vs baseline: 1.4828x; 1.4828x over previous
#include <cuda_runtime.h>
#include <cuda_fp16.h>

#define NN 100000
#define H1D 4
#define CD 8
#define NEG 0.2f

// Persistent device scratch (no allocations allowed in kernel_launch).
__device__ float g_ws[H1D];
__device__ float g_wd[H1D];
__device__ float g_acc1[NN * 8];    // per node: S0,T0,S1,T1,S2,T2,S3,T3 (32B, 32B-aligned)
__device__ float g_acc2[NN * 12];   // per node: S, num[0..7], pad x3 (48B stride)

// Packed layer-2 node record: h2 in fp16 (16B) + als fp32 => 20B used, 32B aligned
struct __align__(32) Node2 {
    __half2 h2[4];
    float   als;
    float   pad[3];
};
__device__ Node2 g_n2[NN];
__device__ float g_ald[NN];

__device__ __forceinline__ void red4(float* addr, float a, float b, float c, float d) {
    asm volatile("red.global.add.v4.f32 [%0], {%1, %2, %3, %4};"
                 :: "l"(addr), "f"(a), "f"(b), "f"(c), "f"(d) : "memory");
}

// ---------------------------------------------------------------------------
// 1) zero accumulators + precompute per-head logit scalars
// ---------------------------------------------------------------------------
__global__ void k_zero_prep(const float* __restrict__ W1,
                            const float* __restrict__ as1,
                            const float* __restrict__ ad1) {
    int t = blockIdx.x * blockDim.x + threadIdx.x;
    int stride = gridDim.x * blockDim.x;
    float4 z = make_float4(0.f, 0.f, 0.f, 0.f);
    float4* a1 = reinterpret_cast<float4*>(g_acc1);   // NN*2 float4
    float4* a2 = reinterpret_cast<float4*>(g_acc2);   // NN*3 float4
    for (int i = t; i < NN * 3; i += stride) {
        a2[i] = z;
        if (i < NN * 2) a1[i] = z;
    }
    if (t < H1D) {
        float s = 0.0f, d = 0.0f;
#pragma unroll
        for (int c = 0; c < CD; c++) {
            float w = W1[t * CD + c];
            s += w * as1[t * CD + c];
            d += w * ad1[t * CD + c];
        }
        g_ws[t] = s;
        g_wd[t] = d;
    }
}

// ---------------------------------------------------------------------------
// 2) layer-1 edge pass: per edge, per head w = exp(lrelu(x_s*ws + x_d*wd));
//    acc1[dst] += {S_h: w, T_h: w*x_s}. Self-loops: t in [E, E+NN).
// ---------------------------------------------------------------------------
__global__ void __launch_bounds__(256) k_edge1(const float* __restrict__ x,
                                               const int* __restrict__ src,
                                               const int* __restrict__ dst,
                                               int E) {
    int t = blockIdx.x * blockDim.x + threadIdx.x;
    int total = E + NN;
    if (t >= total) return;
    int s, d;
    if (t < E) { s = src[t]; d = dst[t]; }
    else       { s = t - E; d = s; }
    float xs = __ldg(&x[s]);
    float xd = __ldg(&x[d]);
    float v[8];
#pragma unroll
    for (int h = 0; h < H1D; h++) {
        float e = xs * g_ws[h] + xd * g_wd[h];
        e = (e > 0.0f) ? e : NEG * e;
        float w = __expf(e);
        v[2 * h]     = w;
        v[2 * h + 1] = w * xs;
    }
    float* base = &g_acc1[(size_t)d * 8];
    red4(base,     v[0], v[1], v[2], v[3]);
    red4(base + 4, v[4], v[5], v[6], v[7]);
}

// ---------------------------------------------------------------------------
// 3) per-node: layer-1 epilogue + relu + W2 GEMV + layer-2 logit precompute.
//    Writes packed fp16 h2 + fp32 als (one 32B record) and ald (dense array).
// ---------------------------------------------------------------------------
__global__ void __launch_bounds__(256) k_mid(const float* __restrict__ W1,
                                             const float* __restrict__ b1,
                                             const float* __restrict__ W2,
                                             const float* __restrict__ as2,
                                             const float* __restrict__ ad2) {
    __shared__ float sW2[32 * 8];
    __shared__ float sW1[32];
    __shared__ float sb1[32];
    __shared__ float sa[16];
    int tid = threadIdx.x;
    if (tid < 256) sW2[tid] = W2[tid];
    if (tid < 32) { sW1[tid] = W1[tid]; sb1[tid] = b1[tid]; }
    if (tid < 8)  { sa[tid] = as2[tid]; sa[8 + tid] = ad2[tid]; }
    __syncthreads();

    int n = blockIdx.x * blockDim.x + tid;
    if (n >= NN) return;

    const float4* a1 = reinterpret_cast<const float4*>(&g_acc1[(size_t)n * 8]);
    float4 p0 = a1[0];  // S0,T0,S1,T1
    float4 p1 = a1[1];  // S2,T2,S3,T3
    float ts[H1D];
    ts[0] = p0.y / p0.x;
    ts[1] = p0.w / p0.z;
    ts[2] = p1.y / p1.x;
    ts[3] = p1.w / p1.z;

    float h2[CD];
#pragma unroll
    for (int c = 0; c < CD; c++) h2[c] = 0.0f;
#pragma unroll
    for (int hc = 0; hc < 32; hc++) {
        float r = sW1[hc] * ts[hc >> 3] + sb1[hc];
        r = fmaxf(r, 0.0f);
#pragma unroll
        for (int c = 0; c < CD; c++) h2[c] += r * sW2[hc * 8 + c];
    }
    float als = 0.0f, ald = 0.0f;
#pragma unroll
    for (int c = 0; c < CD; c++) {
        als += h2[c] * sa[c];
        ald += h2[c] * sa[8 + c];
    }

    // pack h2 -> fp16x8 (one 16B store) + als
    __half2 pk[4];
    pk[0] = __floats2half2_rn(h2[0], h2[1]);
    pk[1] = __floats2half2_rn(h2[2], h2[3]);
    pk[2] = __floats2half2_rn(h2[4], h2[5]);
    pk[3] = __floats2half2_rn(h2[6], h2[7]);
    *reinterpret_cast<uint4*>(g_n2[n].h2) = *reinterpret_cast<const uint4*>(pk);
    g_n2[n].als = als;
    g_ald[n] = ald;
}

// ---------------------------------------------------------------------------
// 4) layer-2 edge pass: w = exp(lrelu(als[s] + ald[d]));
//    acc2[d] += {S: w, num[c]: w*h2[s][c]}
// ---------------------------------------------------------------------------
__global__ void __launch_bounds__(256) k_edge2(const int* __restrict__ src,
                                               const int* __restrict__ dst,
                                               int E) {
    int t = blockIdx.x * blockDim.x + threadIdx.x;
    int total = E + NN;
    if (t >= total) return;
    int s, d;
    if (t < E) { s = src[t]; d = dst[t]; }
    else       { s = t - E; d = s; }

    // single-sector source gather: 16B halves + 4B als (same 32B record)
    uint4 raw = *reinterpret_cast<const uint4*>(g_n2[s].h2);
    __half2 pk[4];
    *reinterpret_cast<uint4*>(pk) = raw;
    float als = g_n2[s].als;
    float ald = __ldg(&g_ald[d]);

    float e = als + ald;
    e = (e > 0.0f) ? e : NEG * e;
    float w = __expf(e);

    float2 f0 = __half22float2(pk[0]);
    float2 f1 = __half22float2(pk[1]);
    float2 f2 = __half22float2(pk[2]);
    float2 f3 = __half22float2(pk[3]);

    float* ab = &g_acc2[(size_t)d * 12];
    red4(ab,     w,        w * f0.x, w * f0.y, w * f1.x);
    red4(ab + 4, w * f1.y, w * f2.x, w * f2.y, w * f3.x);
    atomicAdd(ab + 8, w * f3.y);
}

// ---------------------------------------------------------------------------
// 5) final normalize + bias
// ---------------------------------------------------------------------------
__global__ void __launch_bounds__(256) k_final(float* __restrict__ out,
                                               const float* __restrict__ b2) {
    int t = blockIdx.x * blockDim.x + threadIdx.x;
    if (t >= NN * CD) return;
    int n = t >> 3;
    int c = t & 7;
    const float* ab = &g_acc2[(size_t)n * 12];
    out[t] = ab[1 + c] / ab[0] + b2[c];
}

extern "C" void kernel_launch(void* const* d_in, const int* in_sizes, int n_in,
                              void* d_out, int out_size) {
    const float* x   = (const float*)d_in[0];
    const int*   ei  = (const int*)d_in[1];
    const float* W1  = (const float*)d_in[2];
    const float* as1 = (const float*)d_in[3];
    const float* ad1 = (const float*)d_in[4];
    const float* b1  = (const float*)d_in[5];
    const float* W2  = (const float*)d_in[6];
    const float* as2 = (const float*)d_in[7];
    const float* ad2 = (const float*)d_in[8];
    const float* b2  = (const float*)d_in[9];
    float* out = (float*)d_out;

    int E = in_sizes[1] / 2;
    const int* src = ei;
    const int* dst = ei + E;

    int total = E + NN;
    int tb = 256;

    k_zero_prep<<<1024, tb>>>(W1, as1, ad1);
    k_edge1<<<(total + tb - 1) / tb, tb>>>(x, src, dst, E);
    k_mid<<<(NN + tb - 1) / tb, tb>>>(W1, b1, W2, as2, ad2);
    k_edge2<<<(total + tb - 1) / tb, tb>>>(src, dst, E);
    k_final<<<(NN * CD + tb - 1) / tb, tb>>>(out, b2);
}